// round 4
// baseline (speedup 1.0000x reference)
#include <cuda_runtime.h>

#define NMAX 50000
#define EMAX 800000

// ---------------- scratch (device globals: no runtime allocation) -------------
__device__ float g_hA[NMAX * 64];   // layer-0 output / layer-1 input
__device__ float g_Q[NMAX * 64];
__device__ float g_K[NMAX * 64];
__device__ float g_V[NMAX * 64];
__device__ float g_wV[NMAX * 64];
__device__ float g_Z[NMAX * 4];
__device__ float g_t[NMAX * 64];    // pre-LN temp
__device__ float g_h1[NMAX * 64];
__device__ float g_u[NMAX * 128];   // FFN intermediate

// ---------------- helpers ----------------------------------------------------
__device__ __forceinline__ void red_add_v4(float* addr, float a, float b, float c, float d) {
    asm volatile("red.global.add.v4.f32 [%0], {%1,%2,%3,%4};"
                 :: "l"(addr), "f"(a), "f"(b), "f"(c), "f"(d) : "memory");
}

// ---------------- zero wV / Z -------------------------------------------------
__global__ void zero_wvz_kernel(int n) {
    int i = blockIdx.x * blockDim.x + threadIdx.x;
    if (i < n * 64) g_wV[i] = 0.f;
    if (i < n * 4)  g_Z[i]  = 0.f;
}

// ---------------- generic C[n,64] = A[n,64] @ W[64,64] ------------------------
// block 256, 64-row tile, 4x4 microtile per thread
__global__ void gemm64_kernel(const float* __restrict__ A, const float* __restrict__ W,
                              float* __restrict__ C, int n) {
    __shared__ float As[64][65];
    __shared__ float Ws[64][64];
    int row0 = blockIdx.x * 64;
    int tid = threadIdx.x;

    for (int i = tid; i < 4096; i += 256) Ws[i >> 6][i & 63] = W[i];
    for (int i = tid; i < 4096; i += 256) {
        int r = i >> 6, c = i & 63;
        int gr = row0 + r;
        As[r][c] = (gr < n) ? A[(size_t)gr * 64 + c] : 0.f;
    }
    __syncthreads();

    int tc = tid & 15, tr = tid >> 4;       // 16 col-threads x 16 row-threads
    float acc[4][4] = {};
#pragma unroll 8
    for (int c = 0; c < 64; ++c) {
        float4 w4 = *(const float4*)&Ws[c][tc * 4];
        float a0 = As[tr * 4 + 0][c];
        float a1 = As[tr * 4 + 1][c];
        float a2 = As[tr * 4 + 2][c];
        float a3 = As[tr * 4 + 3][c];
        acc[0][0] += a0 * w4.x; acc[0][1] += a0 * w4.y; acc[0][2] += a0 * w4.z; acc[0][3] += a0 * w4.w;
        acc[1][0] += a1 * w4.x; acc[1][1] += a1 * w4.y; acc[1][2] += a1 * w4.z; acc[1][3] += a1 * w4.w;
        acc[2][0] += a2 * w4.x; acc[2][1] += a2 * w4.y; acc[2][2] += a2 * w4.z; acc[2][3] += a2 * w4.w;
        acc[3][0] += a3 * w4.x; acc[3][1] += a3 * w4.y; acc[3][2] += a3 * w4.z; acc[3][3] += a3 * w4.w;
    }
#pragma unroll
    for (int i = 0; i < 4; ++i) {
        int gr = row0 + tr * 4 + i;
        if (gr < n) {
#pragma unroll
            for (int j = 0; j < 4; ++j)
                C[(size_t)gr * 64 + tc * 4 + j] = acc[i][j];
        }
    }
}

// ---------------- attention output proj + residual ----------------------------
// t = h_in + (wV/(Z+1e-6)) @ WO + bO
__global__ void attn_out_kernel(const float* __restrict__ WO, const float* __restrict__ bO,
                                const float* __restrict__ hin, int n) {
    __shared__ float As[64][65];
    __shared__ float Ws[64][64];
    int row0 = blockIdx.x * 64;
    int tid = threadIdx.x;

    for (int i = tid; i < 4096; i += 256) Ws[i >> 6][i & 63] = WO[i];
    for (int i = tid; i < 4096; i += 256) {
        int r = i >> 6, c = i & 63;
        int gr = row0 + r;
        if (gr < n) {
            float z = g_Z[(size_t)gr * 4 + (c >> 4)] + 1e-6f;
            As[r][c] = g_wV[(size_t)gr * 64 + c] / z;
        } else {
            As[r][c] = 0.f;
        }
    }
    __syncthreads();

    int tc = tid & 15, tr = tid >> 4;
    float acc[4][4] = {};
#pragma unroll 8
    for (int c = 0; c < 64; ++c) {
        float4 w4 = *(const float4*)&Ws[c][tc * 4];
        float a0 = As[tr * 4 + 0][c];
        float a1 = As[tr * 4 + 1][c];
        float a2 = As[tr * 4 + 2][c];
        float a3 = As[tr * 4 + 3][c];
        acc[0][0] += a0 * w4.x; acc[0][1] += a0 * w4.y; acc[0][2] += a0 * w4.z; acc[0][3] += a0 * w4.w;
        acc[1][0] += a1 * w4.x; acc[1][1] += a1 * w4.y; acc[1][2] += a1 * w4.z; acc[1][3] += a1 * w4.w;
        acc[2][0] += a2 * w4.x; acc[2][1] += a2 * w4.y; acc[2][2] += a2 * w4.z; acc[2][3] += a2 * w4.w;
        acc[3][0] += a3 * w4.x; acc[3][1] += a3 * w4.y; acc[3][2] += a3 * w4.z; acc[3][3] += a3 * w4.w;
    }
#pragma unroll
    for (int i = 0; i < 4; ++i) {
        int gr = row0 + tr * 4 + i;
        if (gr < n) {
#pragma unroll
            for (int j = 0; j < 4; ++j) {
                int col = tc * 4 + j;
                g_t[(size_t)gr * 64 + col] = hin[(size_t)gr * 64 + col] + acc[i][j] + bO[col];
            }
        }
    }
}

// ---------------- layer norm --------------------------------------------------
__global__ void ln_kernel(const float* __restrict__ X, const float* __restrict__ g,
                          const float* __restrict__ b, float* __restrict__ Y, int n) {
    int row = blockIdx.x * 8 + (threadIdx.x >> 5);
    int lane = threadIdx.x & 31;
    if (row >= n) return;
    const float* x = X + (size_t)row * 64;
    float x0 = x[lane], x1 = x[lane + 32];
    float s = x0 + x1;
#pragma unroll
    for (int o = 16; o; o >>= 1) s += __shfl_xor_sync(0xffffffffu, s, o);
    float mu = s * (1.f / 64.f);
    float d0 = x0 - mu, d1 = x1 - mu;
    float v = d0 * d0 + d1 * d1;
#pragma unroll
    for (int o = 16; o; o >>= 1) v += __shfl_xor_sync(0xffffffffu, v, o);
    float inv = rsqrtf(v * (1.f / 64.f) + 1e-5f);
    Y[(size_t)row * 64 + lane]      = d0 * inv * g[lane] + b[lane];
    Y[(size_t)row * 64 + lane + 32] = d1 * inv * g[lane + 32] + b[lane + 32];
}

// ---------------- fused edge kernel -------------------------------------------
// per 64-edge tile: Eh = edge_attr @ WE (smem GEMM), then score/exp/messages
// edge_index is int32 (harness dtype): src = ei[e], dst = ei[ne + e]
__global__ void edge_kernel(const float* __restrict__ Ae, const float* __restrict__ WE,
                            const int* __restrict__ ei, int ne) {
    __shared__ float As[64][65];     // edge_attr tile, then reused for Eh
    __shared__ float Ws[64][64];     // WE
    __shared__ int s_src[64], s_dst[64];
    int e0 = blockIdx.x * 64;
    int tid = threadIdx.x;

    for (int i = tid; i < 4096; i += 256) Ws[i >> 6][i & 63] = WE[i];
    for (int i = tid; i < 4096; i += 256) {
        int e = i >> 6, c = i & 63;
        int ge = e0 + e;
        As[e][c] = (ge < ne) ? Ae[(size_t)ge * 64 + c] : 0.f;
    }
    if (tid < 64) {
        int ge = e0 + tid;
        s_src[tid] = (ge < ne) ? ei[ge] : 0;
        s_dst[tid] = (ge < ne) ? ei[ne + ge] : 0;
    }
    __syncthreads();

    // Eh GEMM: 4x4 microtile
    int tc = tid & 15, tr = tid >> 4;
    float acc[4][4] = {};
#pragma unroll 8
    for (int c = 0; c < 64; ++c) {
        float4 w4 = *(const float4*)&Ws[c][tc * 4];
        float a0 = As[tr * 4 + 0][c];
        float a1 = As[tr * 4 + 1][c];
        float a2 = As[tr * 4 + 2][c];
        float a3 = As[tr * 4 + 3][c];
        acc[0][0] += a0 * w4.x; acc[0][1] += a0 * w4.y; acc[0][2] += a0 * w4.z; acc[0][3] += a0 * w4.w;
        acc[1][0] += a1 * w4.x; acc[1][1] += a1 * w4.y; acc[1][2] += a1 * w4.z; acc[1][3] += a1 * w4.w;
        acc[2][0] += a2 * w4.x; acc[2][1] += a2 * w4.y; acc[2][2] += a2 * w4.z; acc[2][3] += a2 * w4.w;
        acc[3][0] += a3 * w4.x; acc[3][1] += a3 * w4.y; acc[3][2] += a3 * w4.z; acc[3][3] += a3 * w4.w;
    }
    __syncthreads();
    // write Eh back into As
#pragma unroll
    for (int i = 0; i < 4; ++i)
#pragma unroll
        for (int j = 0; j < 4; ++j)
            As[tr * 4 + i][tc * 4 + j] = acc[i][j];
    __syncthreads();

    // phase 2: one thread per (edge, head)
    int e = tid >> 2, h = tid & 3;
    int ge = e0 + e;
    if (ge < ne) {
        int sn = s_src[e], dn = s_dst[e];
        const float4* Kp = (const float4*)(g_K + (size_t)sn * 64 + h * 16);
        const float4* Qp = (const float4*)(g_Q + (size_t)dn * 64 + h * 16);
        float s = 0.f;
#pragma unroll
        for (int i = 0; i < 4; ++i) {
            float4 k4 = Kp[i];
            float4 q4 = Qp[i];
            const float* ep = &As[e][h * 16 + i * 4];
            s += k4.x * q4.x * ep[0] + k4.y * q4.y * ep[1] +
                 k4.z * q4.z * ep[2] + k4.w * q4.w * ep[3];
        }
        s *= 0.25f;                        // 1/sqrt(16)
        s = fminf(fmaxf(s, -5.f), 5.f);
        float sc = __expf(s);
        atomicAdd(&g_Z[(size_t)dn * 4 + h], sc);
        const float4* Vp = (const float4*)(g_V + (size_t)sn * 64 + h * 16);
        float* wp = g_wV + (size_t)dn * 64 + h * 16;
#pragma unroll
        for (int i = 0; i < 4; ++i) {
            float4 v = Vp[i];
            red_add_v4(wp + i * 4, v.x * sc, v.y * sc, v.z * sc, v.w * sc);
        }
    }
}

// ---------------- FFN layer 1: u = relu(h1 @ W1[64,128] + b1) ------------------
__global__ void ffn1_kernel(const float* __restrict__ W1, const float* __restrict__ b1, int n) {
    __shared__ float As[32][65];
    __shared__ float Ws[64][128];
    int row0 = blockIdx.x * 32;
    int tid = threadIdx.x;

    for (int i = tid; i < 8192; i += 256) Ws[i >> 7][i & 127] = W1[i];
    for (int i = tid; i < 2048; i += 256) {
        int r = i >> 6, c = i & 63;
        int gr = row0 + r;
        As[r][c] = (gr < n) ? g_h1[(size_t)gr * 64 + c] : 0.f;
    }
    __syncthreads();

    int tc = tid & 31, tr = tid >> 5;   // 32 col-threads x 8 row-threads
    float acc[4][4] = {};
#pragma unroll 8
    for (int c = 0; c < 64; ++c) {
        float4 w4 = *(const float4*)&Ws[c][tc * 4];
        float a0 = As[tr * 4 + 0][c];
        float a1 = As[tr * 4 + 1][c];
        float a2 = As[tr * 4 + 2][c];
        float a3 = As[tr * 4 + 3][c];
        acc[0][0] += a0 * w4.x; acc[0][1] += a0 * w4.y; acc[0][2] += a0 * w4.z; acc[0][3] += a0 * w4.w;
        acc[1][0] += a1 * w4.x; acc[1][1] += a1 * w4.y; acc[1][2] += a1 * w4.z; acc[1][3] += a1 * w4.w;
        acc[2][0] += a2 * w4.x; acc[2][1] += a2 * w4.y; acc[2][2] += a2 * w4.z; acc[2][3] += a2 * w4.w;
        acc[3][0] += a3 * w4.x; acc[3][1] += a3 * w4.y; acc[3][2] += a3 * w4.z; acc[3][3] += a3 * w4.w;
    }
#pragma unroll
    for (int i = 0; i < 4; ++i) {
        int gr = row0 + tr * 4 + i;
        if (gr < n) {
#pragma unroll
            for (int j = 0; j < 4; ++j) {
                int col = tc * 4 + j;
                float y = acc[i][j] + b1[col];
                g_u[(size_t)gr * 128 + col] = fmaxf(y, 0.f);
            }
        }
    }
}

// ---------------- FFN layer 2 + residual: t = h1 + u @ W2[128,64] + b2 ---------
__global__ void ffn2_kernel(const float* __restrict__ W2, const float* __restrict__ b2, int n) {
    __shared__ float As[32][129];
    __shared__ float Ws[64][64];
    int row0 = blockIdx.x * 32;
    int tid = threadIdx.x;

    for (int i = tid; i < 4096; i += 256) {
        int r = i >> 7, c = i & 127;
        int gr = row0 + r;
        As[r][c] = (gr < n) ? g_u[(size_t)gr * 128 + c] : 0.f;
    }

    int tc = tid & 15, tr = tid >> 4;   // 16 col-threads x 16 row-threads (2 rows each)
    float acc[2][4] = {};
    for (int kk = 0; kk < 128; kk += 64) {
        __syncthreads();
        for (int i = tid; i < 4096; i += 256)
            Ws[i >> 6][i & 63] = W2[(size_t)(kk + (i >> 6)) * 64 + (i & 63)];
        __syncthreads();
#pragma unroll 8
        for (int c = 0; c < 64; ++c) {
            float4 w4 = *(const float4*)&Ws[c][tc * 4];
            float a0 = As[tr * 2 + 0][kk + c];
            float a1 = As[tr * 2 + 1][kk + c];
            acc[0][0] += a0 * w4.x; acc[0][1] += a0 * w4.y; acc[0][2] += a0 * w4.z; acc[0][3] += a0 * w4.w;
            acc[1][0] += a1 * w4.x; acc[1][1] += a1 * w4.y; acc[1][2] += a1 * w4.z; acc[1][3] += a1 * w4.w;
        }
    }
#pragma unroll
    for (int i = 0; i < 2; ++i) {
        int gr = row0 + tr * 2 + i;
        if (gr < n) {
#pragma unroll
            for (int j = 0; j < 4; ++j) {
                int col = tc * 4 + j;
                g_t[(size_t)gr * 64 + col] =
                    g_h1[(size_t)gr * 64 + col] + acc[i][j] + b2[col];
            }
        }
    }
}

// ---------------- host orchestration ------------------------------------------
extern "C" void kernel_launch(void* const* d_in, const int* in_sizes, int n_in,
                              void* d_out, int out_size) {
    const float* x   = (const float*)d_in[0];
    const float* ea  = (const float*)d_in[1];
    const int*   ei  = (const int*)d_in[2];   // int32 per harness dtype rules
    const float* WQ  = (const float*)d_in[3];
    const float* WK  = (const float*)d_in[4];
    const float* WE  = (const float*)d_in[5];
    const float* WV  = (const float*)d_in[6];
    const float* WO  = (const float*)d_in[7];
    const float* bO  = (const float*)d_in[8];
    const float* g1  = (const float*)d_in[9];
    const float* be1 = (const float*)d_in[10];
    const float* W1  = (const float*)d_in[11];
    const float* b1  = (const float*)d_in[12];
    const float* W2  = (const float*)d_in[13];
    const float* b2  = (const float*)d_in[14];
    const float* g2  = (const float*)d_in[15];
    const float* be2 = (const float*)d_in[16];
    float* out = (float*)d_out;

    int n  = in_sizes[0] / 64;
    int ne = in_sizes[2] / 2;

    float *p_hA, *p_Q, *p_K, *p_V;
    cudaGetSymbolAddress((void**)&p_hA, g_hA);
    cudaGetSymbolAddress((void**)&p_Q,  g_Q);
    cudaGetSymbolAddress((void**)&p_K,  g_K);
    cudaGetSymbolAddress((void**)&p_V,  g_V);
    float *p_t, *p_h1;
    cudaGetSymbolAddress((void**)&p_t,  g_t);
    cudaGetSymbolAddress((void**)&p_h1, g_h1);

    int nb64 = (n + 63) / 64;
    int nb32 = (n + 31) / 32;
    int nbln = (n + 7) / 8;
    int nbe  = (ne + 63) / 64;

    for (int l = 0; l < 2; ++l) {
        const float* hin  = l ? p_hA : x;
        float*       hout = l ? out : p_hA;
        size_t wo  = (size_t)l * 64 * 64;
        size_t wo1 = (size_t)l * 64 * 128;
        size_t bo  = (size_t)l * 64;
        size_t bo1 = (size_t)l * 128;

        gemm64_kernel<<<nb64, 256>>>(hin, WQ + wo, p_Q, n);
        gemm64_kernel<<<nb64, 256>>>(hin, WK + wo, p_K, n);
        gemm64_kernel<<<nb64, 256>>>(hin, WV + wo, p_V, n);
        zero_wvz_kernel<<<(n * 64 + 255) / 256, 256>>>(n);
        edge_kernel<<<nbe, 256>>>(ea, WE + wo, ei, ne);
        attn_out_kernel<<<nb64, 256>>>(WO + wo, bO + bo, hin, n);
        ln_kernel<<<nbln, 256>>>(p_t, g1 + bo, be1 + bo, p_h1, n);
        ffn1_kernel<<<nb32, 256>>>(W1 + wo1, b1 + bo1, n);
        ffn2_kernel<<<nb32, 256>>>(W2 + wo1, b2 + bo, n);
        ln_kernel<<<nbln, 256>>>(p_t, g2 + bo, be2 + bo, hout, n);
    }
}

// round 5
// speedup vs baseline: 1.0837x; 1.0837x over previous
#include <cuda_runtime.h>

#define NMAX 50000
#define EMAX 800000

// ---------------- scratch (device globals: no runtime allocation) -------------
__device__ float g_hA[NMAX * 64];   // layer-0 output / layer-1 input
__device__ float g_Q[NMAX * 64];
__device__ float g_K[NMAX * 64];
__device__ float g_V[NMAX * 64];
__device__ float g_wV[NMAX * 64];
__device__ float g_Z[NMAX * 4];
__device__ float g_h1[NMAX * 64];

// ---------------- helpers ----------------------------------------------------
__device__ __forceinline__ void red_add_v4(float* addr, float a, float b, float c, float d) {
    asm volatile("red.global.add.v4.f32 [%0], {%1,%2,%3,%4};"
                 :: "l"(addr), "f"(a), "f"(b), "f"(c), "f"(d) : "memory");
}

// ================= fused QKV GEMM + wV/Z zeroing ==============================
// C[p] = A @ W[p] for p in {Q,K,V}; A tile loaded once.
__global__ void qkvz_kernel(const float* __restrict__ A,
                            const float* __restrict__ WQ,
                            const float* __restrict__ WK,
                            const float* __restrict__ WV, int n) {
    __shared__ float As[64][65];
    __shared__ float Ws[64][64];
    int row0 = blockIdx.x * 64;
    int tid = threadIdx.x;

    // zero wV / Z for this block's row range (independent of GEMM)
    for (int i = tid; i < 4096; i += 256) {
        int idx = row0 * 64 + i;
        if (idx < n * 64) g_wV[idx] = 0.f;
    }
    if (tid < 256) {
        int idx = row0 * 4 + tid;
        if (idx < n * 4) g_Z[idx] = 0.f;
    }

    for (int i = tid; i < 4096; i += 256) {
        int r = i >> 6, c = i & 63;
        int gr = row0 + r;
        As[r][c] = (gr < n) ? A[(size_t)gr * 64 + c] : 0.f;
    }

    const float* Wp[3] = {WQ, WK, WV};
    float* Cp[3] = {g_Q, g_K, g_V};
    int tc = tid & 15, tr = tid >> 4;

    for (int p = 0; p < 3; ++p) {
        __syncthreads();   // As ready (p=0) / previous Ws consumed (p>0)
        for (int i = tid; i < 4096; i += 256) Ws[i >> 6][i & 63] = Wp[p][i];
        __syncthreads();

        float acc[4][4] = {};
#pragma unroll 8
        for (int c = 0; c < 64; ++c) {
            float4 w4 = *(const float4*)&Ws[c][tc * 4];
            float a0 = As[tr * 4 + 0][c];
            float a1 = As[tr * 4 + 1][c];
            float a2 = As[tr * 4 + 2][c];
            float a3 = As[tr * 4 + 3][c];
            acc[0][0] += a0 * w4.x; acc[0][1] += a0 * w4.y; acc[0][2] += a0 * w4.z; acc[0][3] += a0 * w4.w;
            acc[1][0] += a1 * w4.x; acc[1][1] += a1 * w4.y; acc[1][2] += a1 * w4.z; acc[1][3] += a1 * w4.w;
            acc[2][0] += a2 * w4.x; acc[2][1] += a2 * w4.y; acc[2][2] += a2 * w4.z; acc[2][3] += a2 * w4.w;
            acc[3][0] += a3 * w4.x; acc[3][1] += a3 * w4.y; acc[3][2] += a3 * w4.z; acc[3][3] += a3 * w4.w;
        }
        float* C = Cp[p];
#pragma unroll
        for (int i = 0; i < 4; ++i) {
            int gr = row0 + tr * 4 + i;
            if (gr < n) {
#pragma unroll
                for (int j = 0; j < 4; ++j)
                    C[(size_t)gr * 64 + tc * 4 + j] = acc[i][j];
            }
        }
    }
}

// ================= fused edge kernel ==========================================
// per 64-edge tile: Eh = edge_attr @ WE (smem GEMM), then score/exp/messages
__global__ void edge_kernel(const float* __restrict__ Ae, const float* __restrict__ WE,
                            const int* __restrict__ ei, int ne) {
    __shared__ float As[64][65];     // edge_attr tile, then reused for Eh
    __shared__ float Ws[64][64];     // WE
    __shared__ int s_src[64], s_dst[64];
    int e0 = blockIdx.x * 64;
    int tid = threadIdx.x;

    for (int i = tid; i < 4096; i += 256) Ws[i >> 6][i & 63] = WE[i];
    for (int i = tid; i < 4096; i += 256) {
        int e = i >> 6, c = i & 63;
        int ge = e0 + e;
        As[e][c] = (ge < ne) ? Ae[(size_t)ge * 64 + c] : 0.f;
    }
    if (tid < 64) {
        int ge = e0 + tid;
        s_src[tid] = (ge < ne) ? ei[ge] : 0;
        s_dst[tid] = (ge < ne) ? ei[ne + ge] : 0;
    }
    __syncthreads();

    int tc = tid & 15, tr = tid >> 4;
    float acc[4][4] = {};
#pragma unroll 8
    for (int c = 0; c < 64; ++c) {
        float4 w4 = *(const float4*)&Ws[c][tc * 4];
        float a0 = As[tr * 4 + 0][c];
        float a1 = As[tr * 4 + 1][c];
        float a2 = As[tr * 4 + 2][c];
        float a3 = As[tr * 4 + 3][c];
        acc[0][0] += a0 * w4.x; acc[0][1] += a0 * w4.y; acc[0][2] += a0 * w4.z; acc[0][3] += a0 * w4.w;
        acc[1][0] += a1 * w4.x; acc[1][1] += a1 * w4.y; acc[1][2] += a1 * w4.z; acc[1][3] += a1 * w4.w;
        acc[2][0] += a2 * w4.x; acc[2][1] += a2 * w4.y; acc[2][2] += a2 * w4.z; acc[2][3] += a2 * w4.w;
        acc[3][0] += a3 * w4.x; acc[3][1] += a3 * w4.y; acc[3][2] += a3 * w4.z; acc[3][3] += a3 * w4.w;
    }
    __syncthreads();
#pragma unroll
    for (int i = 0; i < 4; ++i)
#pragma unroll
        for (int j = 0; j < 4; ++j)
            As[tr * 4 + i][tc * 4 + j] = acc[i][j];
    __syncthreads();

    // phase 2: one thread per (edge, head)
    int e = tid >> 2, h = tid & 3;
    int ge = e0 + e;
    if (ge < ne) {
        int sn = s_src[e], dn = s_dst[e];
        const float4* Kp = (const float4*)(g_K + (size_t)sn * 64 + h * 16);
        const float4* Qp = (const float4*)(g_Q + (size_t)dn * 64 + h * 16);
        float s = 0.f;
#pragma unroll
        for (int i = 0; i < 4; ++i) {
            float4 k4 = Kp[i];
            float4 q4 = Qp[i];
            const float* ep = &As[e][h * 16 + i * 4];
            s += k4.x * q4.x * ep[0] + k4.y * q4.y * ep[1] +
                 k4.z * q4.z * ep[2] + k4.w * q4.w * ep[3];
        }
        s *= 0.25f;                        // 1/sqrt(16)
        s = fminf(fmaxf(s, -5.f), 5.f);
        float sc = __expf(s);
        atomicAdd(&g_Z[(size_t)dn * 4 + h], sc);
        const float4* Vp = (const float4*)(g_V + (size_t)sn * 64 + h * 16);
        float* wp = g_wV + (size_t)dn * 64 + h * 16;
#pragma unroll
        for (int i = 0; i < 4; ++i) {
            float4 v = Vp[i];
            red_add_v4(wp + i * 4, v.x * sc, v.y * sc, v.z * sc, v.w * sc);
        }
    }
}

// ================= attn out-proj + residual + LayerNorm1 ======================
// h1 = LN(hin + (wV/(Z+1e-6)) @ WO + bO)
__global__ void attn_ln_kernel(const float* __restrict__ WO, const float* __restrict__ bO,
                               const float* __restrict__ g, const float* __restrict__ be,
                               const float* __restrict__ hin, int n) {
    __shared__ float As[64][65];
    __shared__ float Ws[64][64];
    int row0 = blockIdx.x * 64;
    int tid = threadIdx.x;

    for (int i = tid; i < 4096; i += 256) Ws[i >> 6][i & 63] = WO[i];
    for (int i = tid; i < 4096; i += 256) {
        int r = i >> 6, c = i & 63;
        int gr = row0 + r;
        if (gr < n) {
            float z = g_Z[(size_t)gr * 4 + (c >> 4)] + 1e-6f;
            As[r][c] = g_wV[(size_t)gr * 64 + c] / z;
        } else {
            As[r][c] = 0.f;
        }
    }
    __syncthreads();

    int tc = tid & 15, tr = tid >> 4;
    float acc[4][4] = {};
#pragma unroll 8
    for (int c = 0; c < 64; ++c) {
        float4 w4 = *(const float4*)&Ws[c][tc * 4];
        float a0 = As[tr * 4 + 0][c];
        float a1 = As[tr * 4 + 1][c];
        float a2 = As[tr * 4 + 2][c];
        float a3 = As[tr * 4 + 3][c];
        acc[0][0] += a0 * w4.x; acc[0][1] += a0 * w4.y; acc[0][2] += a0 * w4.z; acc[0][3] += a0 * w4.w;
        acc[1][0] += a1 * w4.x; acc[1][1] += a1 * w4.y; acc[1][2] += a1 * w4.z; acc[1][3] += a1 * w4.w;
        acc[2][0] += a2 * w4.x; acc[2][1] += a2 * w4.y; acc[2][2] += a2 * w4.z; acc[2][3] += a2 * w4.w;
        acc[3][0] += a3 * w4.x; acc[3][1] += a3 * w4.y; acc[3][2] += a3 * w4.z; acc[3][3] += a3 * w4.w;
    }
    __syncthreads();   // all As reads done; reuse As for t

#pragma unroll
    for (int i = 0; i < 4; ++i) {
        int gr = row0 + tr * 4 + i;
        if (gr < n) {
#pragma unroll
            for (int j = 0; j < 4; ++j) {
                int col = tc * 4 + j;
                As[tr * 4 + i][col] = hin[(size_t)gr * 64 + col] + acc[i][j] + bO[col];
            }
        }
    }
    __syncthreads();

    // LayerNorm: 8 warps x 8 rows
    int w = tid >> 5, lane = tid & 31;
    for (int i = 0; i < 8; ++i) {
        int r = w * 8 + i;
        int gr = row0 + r;
        if (gr >= n) break;
        float x0 = As[r][lane], x1 = As[r][lane + 32];
        float s = x0 + x1;
#pragma unroll
        for (int o = 16; o; o >>= 1) s += __shfl_xor_sync(0xffffffffu, s, o);
        float mu = s * (1.f / 64.f);
        float d0 = x0 - mu, d1 = x1 - mu;
        float v = d0 * d0 + d1 * d1;
#pragma unroll
        for (int o = 16; o; o >>= 1) v += __shfl_xor_sync(0xffffffffu, v, o);
        float inv = rsqrtf(v * (1.f / 64.f) + 1e-5f);
        g_h1[(size_t)gr * 64 + lane]      = d0 * inv * g[lane] + be[lane];
        g_h1[(size_t)gr * 64 + lane + 32] = d1 * inv * g[lane + 32] + be[lane + 32];
    }
}

// ================= fused FFN (W1+relu, W2) + residual + LayerNorm2 ============
// hout = LN(h1 + relu(h1 @ W1 + b1) @ W2 + b2)
// 32 rows per block, u kept in smem.
__global__ void ffn_ln_kernel(const float* __restrict__ W1, const float* __restrict__ b1,
                              const float* __restrict__ W2, const float* __restrict__ b2,
                              const float* __restrict__ g, const float* __restrict__ be,
                              float* __restrict__ hout, int n) {
    __shared__ float h1s[32][65];
    __shared__ float Us[32][133];
    __shared__ float Ws[64][64];
    int row0 = blockIdx.x * 32;
    int tid = threadIdx.x;
    int tc = tid & 15, tr = tid >> 4;   // 16 x 16, 2 rows per thread

    for (int i = tid; i < 2048; i += 256) {
        int r = i >> 6, c = i & 63;
        int gr = row0 + r;
        h1s[r][c] = (gr < n) ? g_h1[(size_t)gr * 64 + c] : 0.f;
    }

    // ---- GEMM1: u = relu(h1 @ W1 + b1), two 64-col halves ----
    for (int nh = 0; nh < 2; ++nh) {
        __syncthreads();
        for (int i = tid; i < 4096; i += 256)
            Ws[i >> 6][i & 63] = W1[(size_t)(i >> 6) * 128 + nh * 64 + (i & 63)];
        __syncthreads();

        float acc[2][4] = {};
#pragma unroll 8
        for (int c = 0; c < 64; ++c) {
            float4 w4 = *(const float4*)&Ws[c][tc * 4];
            float a0 = h1s[tr * 2 + 0][c];
            float a1 = h1s[tr * 2 + 1][c];
            acc[0][0] += a0 * w4.x; acc[0][1] += a0 * w4.y; acc[0][2] += a0 * w4.z; acc[0][3] += a0 * w4.w;
            acc[1][0] += a1 * w4.x; acc[1][1] += a1 * w4.y; acc[1][2] += a1 * w4.z; acc[1][3] += a1 * w4.w;
        }
#pragma unroll
        for (int i = 0; i < 2; ++i)
#pragma unroll
            for (int j = 0; j < 4; ++j) {
                int col = nh * 64 + tc * 4 + j;
                Us[tr * 2 + i][col] = fmaxf(acc[i][j] + b1[col], 0.f);
            }
    }

    // ---- GEMM2: t = h1 + u @ W2 + b2, two 64-k halves ----
    float acc2[2][4] = {};
    for (int kk = 0; kk < 2; ++kk) {
        __syncthreads();
        for (int i = tid; i < 4096; i += 256)
            Ws[i >> 6][i & 63] = W2[(size_t)(kk * 64 + (i >> 6)) * 64 + (i & 63)];
        __syncthreads();
#pragma unroll 8
        for (int c = 0; c < 64; ++c) {
            float4 w4 = *(const float4*)&Ws[c][tc * 4];
            float a0 = Us[tr * 2 + 0][kk * 64 + c];
            float a1 = Us[tr * 2 + 1][kk * 64 + c];
            acc2[0][0] += a0 * w4.x; acc2[0][1] += a0 * w4.y; acc2[0][2] += a0 * w4.z; acc2[0][3] += a0 * w4.w;
            acc2[1][0] += a1 * w4.x; acc2[1][1] += a1 * w4.y; acc2[1][2] += a1 * w4.z; acc2[1][3] += a1 * w4.w;
        }
    }
    __syncthreads();   // all Us reads done; reuse cols 0..63 for t
#pragma unroll
    for (int i = 0; i < 2; ++i) {
        int r = tr * 2 + i;
#pragma unroll
        for (int j = 0; j < 4; ++j) {
            int col = tc * 4 + j;
            Us[r][col] = h1s[r][col] + acc2[i][j] + b2[col];
        }
    }
    __syncthreads();

    // LayerNorm2: 8 warps x 4 rows
    int w = tid >> 5, lane = tid & 31;
    for (int i = 0; i < 4; ++i) {
        int r = w * 4 + i;
        int gr = row0 + r;
        if (gr >= n) break;
        float x0 = Us[r][lane], x1 = Us[r][lane + 32];
        float s = x0 + x1;
#pragma unroll
        for (int o = 16; o; o >>= 1) s += __shfl_xor_sync(0xffffffffu, s, o);
        float mu = s * (1.f / 64.f);
        float d0 = x0 - mu, d1 = x1 - mu;
        float v = d0 * d0 + d1 * d1;
#pragma unroll
        for (int o = 16; o; o >>= 1) v += __shfl_xor_sync(0xffffffffu, v, o);
        float inv = rsqrtf(v * (1.f / 64.f) + 1e-5f);
        hout[(size_t)gr * 64 + lane]      = d0 * inv * g[lane] + be[lane];
        hout[(size_t)gr * 64 + lane + 32] = d1 * inv * g[lane + 32] + be[lane + 32];
    }
}

// ---------------- host orchestration ------------------------------------------
extern "C" void kernel_launch(void* const* d_in, const int* in_sizes, int n_in,
                              void* d_out, int out_size) {
    const float* x   = (const float*)d_in[0];
    const float* ea  = (const float*)d_in[1];
    const int*   ei  = (const int*)d_in[2];   // int32 per harness dtype rules
    const float* WQ  = (const float*)d_in[3];
    const float* WK  = (const float*)d_in[4];
    const float* WE  = (const float*)d_in[5];
    const float* WV  = (const float*)d_in[6];
    const float* WO  = (const float*)d_in[7];
    const float* bO  = (const float*)d_in[8];
    const float* g1  = (const float*)d_in[9];
    const float* be1 = (const float*)d_in[10];
    const float* W1  = (const float*)d_in[11];
    const float* b1  = (const float*)d_in[12];
    const float* W2  = (const float*)d_in[13];
    const float* b2  = (const float*)d_in[14];
    const float* g2  = (const float*)d_in[15];
    const float* be2 = (const float*)d_in[16];
    float* out = (float*)d_out;

    int n  = in_sizes[0] / 64;
    int ne = in_sizes[2] / 2;

    float* p_hA;
    cudaGetSymbolAddress((void**)&p_hA, g_hA);

    int nb64 = (n + 63) / 64;
    int nb32 = (n + 31) / 32;
    int nbe  = (ne + 63) / 64;

    for (int l = 0; l < 2; ++l) {
        const float* hin  = l ? p_hA : x;
        float*       hout = l ? out : p_hA;
        size_t wo  = (size_t)l * 64 * 64;
        size_t wo1 = (size_t)l * 64 * 128;
        size_t bo  = (size_t)l * 64;
        size_t bo1 = (size_t)l * 128;

        qkvz_kernel<<<nb64, 256>>>(hin, WQ + wo, WK + wo, WV + wo, n);
        edge_kernel<<<nbe, 256>>>(ea, WE + wo, ei, ne);
        attn_ln_kernel<<<nb64, 256>>>(WO + wo, bO + bo, g1 + bo, be1 + bo, hin, n);
        ffn_ln_kernel<<<nb32, 256>>>(W1 + wo1, b1 + bo1, W2 + wo1, b2 + bo,
                                     g2 + bo, be2 + bo, hout, n);
    }
}

// round 6
// speedup vs baseline: 1.1438x; 1.0554x over previous
#include <cuda_runtime.h>

#define NMAX 50000
#define EMAX 800000

// ---------------- scratch (device globals: no runtime allocation) -------------
__device__ float g_hA[NMAX * 64];   // layer-0 output / layer-1 input
__device__ float g_Q[NMAX * 64];
__device__ float g_K[NMAX * 64];
__device__ float g_V[NMAX * 64];
__device__ float g_wV[NMAX * 64];
__device__ float g_Z[NMAX * 4];
__device__ float g_h1[NMAX * 64];

// ---------------- helpers ----------------------------------------------------
__device__ __forceinline__ void red_add_v4(float* addr, float a, float b, float c, float d) {
    asm volatile("red.global.add.v4.f32 [%0], {%1,%2,%3,%4};"
                 :: "l"(addr), "f"(a), "f"(b), "f"(c), "f"(d) : "memory");
}

// 4x4 rank-1 update macro: acc[i][j] += a4[i] * w4[j]
#define RANK1(acc, a4, w4)                                                              \
    acc[0][0] += a4.x * w4.x; acc[0][1] += a4.x * w4.y;                                 \
    acc[0][2] += a4.x * w4.z; acc[0][3] += a4.x * w4.w;                                 \
    acc[1][0] += a4.y * w4.x; acc[1][1] += a4.y * w4.y;                                 \
    acc[1][2] += a4.y * w4.z; acc[1][3] += a4.y * w4.w;                                 \
    acc[2][0] += a4.z * w4.x; acc[2][1] += a4.z * w4.y;                                 \
    acc[2][2] += a4.z * w4.z; acc[2][3] += a4.z * w4.w;                                 \
    acc[3][0] += a4.w * w4.x; acc[3][1] += a4.w * w4.y;                                 \
    acc[3][2] += a4.w * w4.z; acc[3][3] += a4.w * w4.w;

// ================= fused QKV GEMM + wV/Z zeroing ==============================
__global__ void qkvz_kernel(const float* __restrict__ A,
                            const float* __restrict__ WQ,
                            const float* __restrict__ WK,
                            const float* __restrict__ WV, int n) {
    __shared__ float Ast[64][68];   // A transposed: Ast[c][row]
    __shared__ float Ws[64][64];
    int row0 = blockIdx.x * 64;
    int tid = threadIdx.x;

    // zero wV / Z for this block's row range
    for (int i = tid; i < 4096; i += 256) {
        int idx = row0 * 64 + i;
        if (idx < n * 64) g_wV[idx] = 0.f;
    }
    {
        int idx = row0 * 4 + tid;
        if (idx < n * 4) g_Z[idx] = 0.f;
    }

    for (int i = tid; i < 4096; i += 256) {
        int r = i >> 6, c = i & 63;
        int gr = row0 + r;
        Ast[c][r] = (gr < n) ? A[(size_t)gr * 64 + c] : 0.f;
    }

    int tc = tid & 15, tr = tid >> 4;

#pragma unroll
    for (int p = 0; p < 3; ++p) {
        const float* W = (p == 0) ? WQ : (p == 1) ? WK : WV;
        float* C = (p == 0) ? g_Q : (p == 1) ? g_K : g_V;
        __syncthreads();   // Ast ready (p=0) / previous Ws consumed (p>0)
        for (int i = tid; i < 4096; i += 256) Ws[i >> 6][i & 63] = W[i];
        __syncthreads();

        float acc[4][4] = {};
#pragma unroll 16
        for (int c = 0; c < 64; ++c) {
            float4 a4 = *(const float4*)&Ast[c][tr * 4];
            float4 w4 = *(const float4*)&Ws[c][tc * 4];
            RANK1(acc, a4, w4)
        }
#pragma unroll
        for (int i = 0; i < 4; ++i) {
            int gr = row0 + tr * 4 + i;
            if (gr < n) {
                float4 o = make_float4(acc[i][0], acc[i][1], acc[i][2], acc[i][3]);
                *(float4*)&C[(size_t)gr * 64 + tc * 4] = o;
            }
        }
    }
}

// ================= fused edge kernel ==========================================
// per 64-edge tile: Eh = edge_attr @ WE (smem GEMM), then score/exp/messages
__global__ void edge_kernel(const float* __restrict__ Ae, const float* __restrict__ WE,
                            const int* __restrict__ ei, int ne) {
    __shared__ float Ast[64][68];    // edge_attr transposed
    __shared__ float Ws[64][64];     // WE, then reused for Eh (row-major)
    __shared__ int s_src[64], s_dst[64];
    int e0 = blockIdx.x * 64;
    int tid = threadIdx.x;

    for (int i = tid; i < 4096; i += 256) Ws[i >> 6][i & 63] = WE[i];
    for (int i = tid; i < 4096; i += 256) {
        int e = i >> 6, c = i & 63;
        int ge = e0 + e;
        Ast[c][e] = (ge < ne) ? Ae[(size_t)ge * 64 + c] : 0.f;
    }
    if (tid < 64) {
        int ge = e0 + tid;
        s_src[tid] = (ge < ne) ? ei[ge] : 0;
        s_dst[tid] = (ge < ne) ? ei[ne + ge] : 0;
    }
    __syncthreads();

    int tc = tid & 15, tr = tid >> 4;
    float acc[4][4] = {};
#pragma unroll 16
    for (int c = 0; c < 64; ++c) {
        float4 a4 = *(const float4*)&Ast[c][tr * 4];
        float4 w4 = *(const float4*)&Ws[c][tc * 4];
        RANK1(acc, a4, w4)
    }
    __syncthreads();
    // stash Eh row-major into Ws (WE no longer needed)
#pragma unroll
    for (int i = 0; i < 4; ++i) {
        float4 o = make_float4(acc[i][0], acc[i][1], acc[i][2], acc[i][3]);
        *(float4*)&Ws[tr * 4 + i][tc * 4] = o;
    }
    __syncthreads();

    // phase 2: one thread per (edge, head)
    int e = tid >> 2, h = tid & 3;
    int ge = e0 + e;
    if (ge < ne) {
        int sn = s_src[e], dn = s_dst[e];
        const float4* Kp = (const float4*)(g_K + (size_t)sn * 64 + h * 16);
        const float4* Qp = (const float4*)(g_Q + (size_t)dn * 64 + h * 16);
        float s = 0.f;
#pragma unroll
        for (int i = 0; i < 4; ++i) {
            float4 k4 = Kp[i];
            float4 q4 = Qp[i];
            const float* ep = &Ws[e][h * 16 + i * 4];
            s += k4.x * q4.x * ep[0] + k4.y * q4.y * ep[1] +
                 k4.z * q4.z * ep[2] + k4.w * q4.w * ep[3];
        }
        s *= 0.25f;                        // 1/sqrt(16)
        s = fminf(fmaxf(s, -5.f), 5.f);
        float sc = __expf(s);
        atomicAdd(&g_Z[(size_t)dn * 4 + h], sc);
        const float4* Vp = (const float4*)(g_V + (size_t)sn * 64 + h * 16);
        float* wp = g_wV + (size_t)dn * 64 + h * 16;
#pragma unroll
        for (int i = 0; i < 4; ++i) {
            float4 v = Vp[i];
            red_add_v4(wp + i * 4, v.x * sc, v.y * sc, v.z * sc, v.w * sc);
        }
    }
}

// ================= attn out-proj + residual + LayerNorm1 ======================
// h1 = LN(hin + (wV/(Z+1e-6)) @ WO + bO)
__global__ void attn_ln_kernel(const float* __restrict__ WO, const float* __restrict__ bO,
                               const float* __restrict__ g, const float* __restrict__ be,
                               const float* __restrict__ hin, int n) {
    __shared__ float Ast[64][68];   // (wV/Z) transposed, then t transposed
    __shared__ float Ws[64][64];
    int row0 = blockIdx.x * 64;
    int tid = threadIdx.x;

    for (int i = tid; i < 4096; i += 256) Ws[i >> 6][i & 63] = WO[i];
    for (int i = tid; i < 4096; i += 256) {
        int r = i >> 6, c = i & 63;
        int gr = row0 + r;
        if (gr < n) {
            float z = g_Z[(size_t)gr * 4 + (c >> 4)] + 1e-6f;
            Ast[c][r] = g_wV[(size_t)gr * 64 + c] / z;
        } else {
            Ast[c][r] = 0.f;
        }
    }
    __syncthreads();

    int tc = tid & 15, tr = tid >> 4;
    float acc[4][4] = {};
#pragma unroll 16
    for (int c = 0; c < 64; ++c) {
        float4 a4 = *(const float4*)&Ast[c][tr * 4];
        float4 w4 = *(const float4*)&Ws[c][tc * 4];
        RANK1(acc, a4, w4)
    }
    __syncthreads();   // all Ast reads done; reuse Ast (transposed) for t

#pragma unroll
    for (int i = 0; i < 4; ++i) {
        int gr = row0 + tr * 4 + i;
        if (gr < n) {
            float4 h4 = *(const float4*)&hin[(size_t)gr * 64 + tc * 4];
            Ast[tc * 4 + 0][tr * 4 + i] = h4.x + acc[i][0] + bO[tc * 4 + 0];
            Ast[tc * 4 + 1][tr * 4 + i] = h4.y + acc[i][1] + bO[tc * 4 + 1];
            Ast[tc * 4 + 2][tr * 4 + i] = h4.z + acc[i][2] + bO[tc * 4 + 2];
            Ast[tc * 4 + 3][tr * 4 + i] = h4.w + acc[i][3] + bO[tc * 4 + 3];
        }
    }
    __syncthreads();

    // LayerNorm: 8 warps x 8 rows, reading columns of Ast
    int w = tid >> 5, lane = tid & 31;
    for (int i = 0; i < 8; ++i) {
        int r = w * 8 + i;
        int gr = row0 + r;
        if (gr >= n) break;
        float x0 = Ast[lane][r], x1 = Ast[lane + 32][r];
        float s = x0 + x1;
#pragma unroll
        for (int o = 16; o; o >>= 1) s += __shfl_xor_sync(0xffffffffu, s, o);
        float mu = s * (1.f / 64.f);
        float d0 = x0 - mu, d1 = x1 - mu;
        float v = d0 * d0 + d1 * d1;
#pragma unroll
        for (int o = 16; o; o >>= 1) v += __shfl_xor_sync(0xffffffffu, v, o);
        float inv = rsqrtf(v * (1.f / 64.f) + 1e-5f);
        g_h1[(size_t)gr * 64 + lane]      = d0 * inv * g[lane] + be[lane];
        g_h1[(size_t)gr * 64 + lane + 32] = d1 * inv * g[lane + 32] + be[lane + 32];
    }
}

// ================= fused FFN (W1+relu, W2) + residual + LayerNorm2 ============
// hout = LN(h1 + relu(h1 @ W1 + b1) @ W2 + b2)
// 64 rows per block; h1 and u kept transposed in smem.
__global__ void ffn_ln_kernel(const float* __restrict__ W1, const float* __restrict__ b1,
                              const float* __restrict__ W2, const float* __restrict__ b2,
                              const float* __restrict__ g, const float* __restrict__ be,
                              float* __restrict__ hout, int n) {
    __shared__ float h1t[64][68];    // h1 transposed, later t transposed
    __shared__ float Ut[128][68];    // u transposed
    __shared__ float Ws[64][64];
    int row0 = blockIdx.x * 64;
    int tid = threadIdx.x;
    int tc = tid & 15, tr = tid >> 4;

    for (int i = tid; i < 4096; i += 256) {
        int r = i >> 6, c = i & 63;
        int gr = row0 + r;
        h1t[c][r] = (gr < n) ? g_h1[(size_t)gr * 64 + c] : 0.f;
    }

    // ---- GEMM1: u = relu(h1 @ W1 + b1), two 64-col halves ----
#pragma unroll
    for (int nh = 0; nh < 2; ++nh) {
        __syncthreads();
        for (int i = tid; i < 4096; i += 256)
            Ws[i >> 6][i & 63] = W1[(size_t)(i >> 6) * 128 + nh * 64 + (i & 63)];
        __syncthreads();

        float acc[4][4] = {};
#pragma unroll 16
        for (int c = 0; c < 64; ++c) {
            float4 a4 = *(const float4*)&h1t[c][tr * 4];
            float4 w4 = *(const float4*)&Ws[c][tc * 4];
            RANK1(acc, a4, w4)
        }
#pragma unroll
        for (int j = 0; j < 4; ++j) {
            int col = nh * 64 + tc * 4 + j;
            float bb = b1[col];
            Ut[col][tr * 4 + 0] = fmaxf(acc[0][j] + bb, 0.f);
            Ut[col][tr * 4 + 1] = fmaxf(acc[1][j] + bb, 0.f);
            Ut[col][tr * 4 + 2] = fmaxf(acc[2][j] + bb, 0.f);
            Ut[col][tr * 4 + 3] = fmaxf(acc[3][j] + bb, 0.f);
        }
    }

    // ---- GEMM2: t = h1 + u @ W2 + b2, two 64-k halves ----
    float acc2[4][4] = {};
#pragma unroll
    for (int kk = 0; kk < 2; ++kk) {
        __syncthreads();
        for (int i = tid; i < 4096; i += 256)
            Ws[i >> 6][i & 63] = W2[(size_t)(kk * 64 + (i >> 6)) * 64 + (i & 63)];
        __syncthreads();
#pragma unroll 16
        for (int c = 0; c < 64; ++c) {
            float4 a4 = *(const float4*)&Ut[kk * 64 + c][tr * 4];
            float4 w4 = *(const float4*)&Ws[c][tc * 4];
            RANK1(acc2, a4, w4)
        }
    }
    __syncthreads();   // all reads done
#pragma unroll
    for (int j = 0; j < 4; ++j) {
        int col = tc * 4 + j;
        float bb = b2[col];
#pragma unroll
        for (int i = 0; i < 4; ++i) {
            int r = tr * 4 + i;
            h1t[col][r] = h1t[col][r] + acc2[i][j] + bb;
        }
    }
    __syncthreads();

    // LayerNorm2: 8 warps x 8 rows
    int w = tid >> 5, lane = tid & 31;
    for (int i = 0; i < 8; ++i) {
        int r = w * 8 + i;
        int gr = row0 + r;
        if (gr >= n) break;
        float x0 = h1t[lane][r], x1 = h1t[lane + 32][r];
        float s = x0 + x1;
#pragma unroll
        for (int o = 16; o; o >>= 1) s += __shfl_xor_sync(0xffffffffu, s, o);
        float mu = s * (1.f / 64.f);
        float d0 = x0 - mu, d1 = x1 - mu;
        float v = d0 * d0 + d1 * d1;
#pragma unroll
        for (int o = 16; o; o >>= 1) v += __shfl_xor_sync(0xffffffffu, v, o);
        float inv = rsqrtf(v * (1.f / 64.f) + 1e-5f);
        hout[(size_t)gr * 64 + lane]      = d0 * inv * g[lane] + be[lane];
        hout[(size_t)gr * 64 + lane + 32] = d1 * inv * g[lane + 32] + be[lane + 32];
    }
}

// ---------------- host orchestration ------------------------------------------
extern "C" void kernel_launch(void* const* d_in, const int* in_sizes, int n_in,
                              void* d_out, int out_size) {
    const float* x   = (const float*)d_in[0];
    const float* ea  = (const float*)d_in[1];
    const int*   ei  = (const int*)d_in[2];   // int32 per harness dtype rules
    const float* WQ  = (const float*)d_in[3];
    const float* WK  = (const float*)d_in[4];
    const float* WE  = (const float*)d_in[5];
    const float* WV  = (const float*)d_in[6];
    const float* WO  = (const float*)d_in[7];
    const float* bO  = (const float*)d_in[8];
    const float* g1  = (const float*)d_in[9];
    const float* be1 = (const float*)d_in[10];
    const float* W1  = (const float*)d_in[11];
    const float* b1  = (const float*)d_in[12];
    const float* W2  = (const float*)d_in[13];
    const float* b2  = (const float*)d_in[14];
    const float* g2  = (const float*)d_in[15];
    const float* be2 = (const float*)d_in[16];
    float* out = (float*)d_out;

    int n  = in_sizes[0] / 64;
    int ne = in_sizes[2] / 2;

    float* p_hA;
    cudaGetSymbolAddress((void**)&p_hA, g_hA);

    int nb64 = (n + 63) / 64;
    int nbe  = (ne + 63) / 64;

    for (int l = 0; l < 2; ++l) {
        const float* hin  = l ? p_hA : x;
        float*       hout = l ? out : p_hA;
        size_t wo  = (size_t)l * 64 * 64;
        size_t wo1 = (size_t)l * 64 * 128;
        size_t bo  = (size_t)l * 64;
        size_t bo1 = (size_t)l * 128;

        qkvz_kernel<<<nb64, 256>>>(hin, WQ + wo, WK + wo, WV + wo, n);
        edge_kernel<<<nbe, 256>>>(ea, WE + wo, ei, ne);
        attn_ln_kernel<<<nb64, 256>>>(WO + wo, bO + bo, g1 + bo, be1 + bo, hin, n);
        ffn_ln_kernel<<<nb64, 256>>>(W1 + wo1, b1 + bo1, W2 + wo1, b2 + bo,
                                     g2 + bo, be2 + bo, hout, n);
    }
}

// round 7
// speedup vs baseline: 1.2896x; 1.1274x over previous
#include <cuda_runtime.h>
#include <cstdint>

#define NMAX 50000
#define EMAX 800000

// ---------------- scratch (device globals: no runtime allocation) -------------
__device__ float g_hA[NMAX * 64];   // layer-0 output / layer-1 input
__device__ float g_Q[NMAX * 64];
__device__ float g_K[NMAX * 64];
__device__ float g_V[NMAX * 64];
__device__ float g_wV[NMAX * 64];
__device__ float g_Z[NMAX * 4];
__device__ float g_h1[NMAX * 64];

// ---------------- helpers ----------------------------------------------------
__device__ __forceinline__ void red_add_v4(float* addr, float a, float b, float c, float d) {
    asm volatile("red.global.add.v4.f32 [%0], {%1,%2,%3,%4};"
                 :: "l"(addr), "f"(a), "f"(b), "f"(c), "f"(d) : "memory");
}

__device__ __forceinline__ uint32_t f2tf32(float x) {
    uint32_t r; asm("cvt.rna.tf32.f32 %0, %1;" : "=r"(r) : "f"(x)); return r;
}

__device__ __forceinline__ void mma8(float c[4], const uint32_t a[4], const uint32_t b[2]) {
    asm("mma.sync.aligned.m16n8k8.row.col.f32.tf32.tf32.f32 "
        "{%0,%1,%2,%3}, {%4,%5,%6,%7}, {%8,%9}, {%0,%1,%2,%3};"
        : "+f"(c[0]), "+f"(c[1]), "+f"(c[2]), "+f"(c[3])
        : "r"(a[0]), "r"(a[1]), "r"(a[2]), "r"(a[3]), "r"(b[0]), "r"(b[1]));
}

// 64x64x64 GEMM chunk on tensor cores with 3xTF32 split (near-fp32 accuracy).
// As: row-major [64][PITCH] (row, k).  Ws: row-major [64][72] (k, n).
// Warp computes C[r0:r0+16][n0:n0+32] into acc[4][4] (4 n-tiles of 8 cols).
// C element map: C[r0+g+8*ci][n0+nt*8+t4*2+cj] = acc[nt][ci*2+cj], g=lane>>2, t4=lane&3.
template<int PITCH>
__device__ __forceinline__ void gemm64_tf32(const float* As, const float* Ws,
                                            float acc[4][4], int r0, int n0) {
    int lane = threadIdx.x & 31;
    int g = lane >> 2, t4 = lane & 3;
#pragma unroll
    for (int k0 = 0; k0 < 64; k0 += 8) {
        float af[4] = {
            As[(r0 + g)     * PITCH + k0 + t4],
            As[(r0 + g + 8) * PITCH + k0 + t4],
            As[(r0 + g)     * PITCH + k0 + t4 + 4],
            As[(r0 + g + 8) * PITCH + k0 + t4 + 4] };
        uint32_t ah[4], al[4];
#pragma unroll
        for (int i = 0; i < 4; ++i) {
            ah[i] = f2tf32(af[i]);
            al[i] = f2tf32(af[i] - __uint_as_float(ah[i]));
        }
#pragma unroll
        for (int nt = 0; nt < 4; ++nt) {
            int n = n0 + nt * 8 + g;
            float b0 = Ws[(k0 + t4)     * 72 + n];
            float b1 = Ws[(k0 + t4 + 4) * 72 + n];
            uint32_t bh[2] = { f2tf32(b0), f2tf32(b1) };
            uint32_t bl[2] = { f2tf32(b0 - __uint_as_float(bh[0])),
                               f2tf32(b1 - __uint_as_float(bh[1])) };
            mma8(acc[nt], ah, bh);
            mma8(acc[nt], ah, bl);
            mma8(acc[nt], al, bh);
        }
    }
}

// ================= fused QKV GEMM + wV/Z zeroing ==============================
__global__ void qkvz_kernel(const float* __restrict__ A,
                            const float* __restrict__ WQ,
                            const float* __restrict__ WK,
                            const float* __restrict__ WV, int n) {
    __shared__ float As[64 * 68];
    __shared__ float Ws[64 * 72];
    int row0 = blockIdx.x * 64;
    int tid = threadIdx.x;
    int w = tid >> 5, lane = tid & 31;
    int g = lane >> 2, t4 = lane & 3;
    int r0 = (w & 3) * 16, n0 = (w >> 2) * 32;

    // zero wV / Z for this block's row range
    for (int i = tid; i < 4096; i += 256) {
        int idx = row0 * 64 + i;
        if (idx < n * 64) g_wV[idx] = 0.f;
    }
    {
        int idx = row0 * 4 + tid;
        if (idx < n * 4) g_Z[idx] = 0.f;
    }

    for (int i = tid; i < 4096; i += 256) {
        int r = i >> 6, c = i & 63;
        int gr = row0 + r;
        As[r * 68 + c] = (gr < n) ? A[(size_t)gr * 64 + c] : 0.f;
    }

#pragma unroll
    for (int p = 0; p < 3; ++p) {
        const float* W = (p == 0) ? WQ : (p == 1) ? WK : WV;
        float* C = (p == 0) ? g_Q : (p == 1) ? g_K : g_V;
        __syncthreads();   // As ready (p=0) / previous Ws reads done (p>0)
        for (int i = tid; i < 4096; i += 256) Ws[(i >> 6) * 72 + (i & 63)] = W[i];
        __syncthreads();

        float acc[4][4] = {};
        gemm64_tf32<68>(As, Ws, acc, r0, n0);

#pragma unroll
        for (int nt = 0; nt < 4; ++nt) {
            int col = n0 + nt * 8 + t4 * 2;
#pragma unroll
            for (int ci = 0; ci < 2; ++ci) {
                int gr = row0 + r0 + g + 8 * ci;
                if (gr < n) {
                    float2 o = make_float2(acc[nt][ci * 2], acc[nt][ci * 2 + 1]);
                    *(float2*)&C[(size_t)gr * 64 + col] = o;
                }
            }
        }
    }
}

// ================= fused edge kernel ==========================================
// per 64-edge tile: Eh = edge_attr @ WE (tensor-core GEMM), then score/exp/msgs
__global__ void edge_kernel(const float* __restrict__ Ae, const float* __restrict__ WE,
                            const int* __restrict__ ei, int ne) {
    __shared__ float As[64 * 68];    // edge_attr rows, then Eh rows
    __shared__ float Ws[64 * 72];    // WE
    __shared__ int s_src[64], s_dst[64];
    int e0 = blockIdx.x * 64;
    int tid = threadIdx.x;
    int w = tid >> 5, lane = tid & 31;
    int g = lane >> 2, t4 = lane & 3;
    int r0 = (w & 3) * 16, n0 = (w >> 2) * 32;

    for (int i = tid; i < 4096; i += 256) Ws[(i >> 6) * 72 + (i & 63)] = WE[i];
    for (int i = tid; i < 4096; i += 256) {
        int e = i >> 6, c = i & 63;
        int ge = e0 + e;
        As[e * 68 + c] = (ge < ne) ? Ae[(size_t)ge * 64 + c] : 0.f;
    }
    if (tid < 64) {
        int ge = e0 + tid;
        s_src[tid] = (ge < ne) ? ei[ge] : 0;
        s_dst[tid] = (ge < ne) ? ei[ne + ge] : 0;
    }
    __syncthreads();

    float acc[4][4] = {};
    gemm64_tf32<68>(As, Ws, acc, r0, n0);
    __syncthreads();   // all As reads done; reuse As for Eh (row-major, pitch 68)
#pragma unroll
    for (int nt = 0; nt < 4; ++nt) {
        int col = n0 + nt * 8 + t4 * 2;
#pragma unroll
        for (int ci = 0; ci < 2; ++ci) {
            As[(r0 + g + 8 * ci) * 68 + col]     = acc[nt][ci * 2];
            As[(r0 + g + 8 * ci) * 68 + col + 1] = acc[nt][ci * 2 + 1];
        }
    }
    __syncthreads();

    // phase 2: one thread per (edge, head)
    int e = tid >> 2, h = tid & 3;
    int ge = e0 + e;
    if (ge < ne) {
        int sn = s_src[e], dn = s_dst[e];
        const float4* Kp = (const float4*)(g_K + (size_t)sn * 64 + h * 16);
        const float4* Qp = (const float4*)(g_Q + (size_t)dn * 64 + h * 16);
        float s = 0.f;
#pragma unroll
        for (int i = 0; i < 4; ++i) {
            float4 k4 = Kp[i];
            float4 q4 = Qp[i];
            const float* ep = &As[e * 68 + h * 16 + i * 4];
            s += k4.x * q4.x * ep[0] + k4.y * q4.y * ep[1] +
                 k4.z * q4.z * ep[2] + k4.w * q4.w * ep[3];
        }
        s *= 0.25f;                        // 1/sqrt(16)
        s = fminf(fmaxf(s, -5.f), 5.f);
        float sc = __expf(s);
        atomicAdd(&g_Z[(size_t)dn * 4 + h], sc);
        const float4* Vp = (const float4*)(g_V + (size_t)sn * 64 + h * 16);
        float* wp = g_wV + (size_t)dn * 64 + h * 16;
#pragma unroll
        for (int i = 0; i < 4; ++i) {
            float4 v = Vp[i];
            red_add_v4(wp + i * 4, v.x * sc, v.y * sc, v.z * sc, v.w * sc);
        }
    }
}

// ================= attn out-proj + residual + LayerNorm1 ======================
// h1 = LN(hin + (wV/(Z+1e-6)) @ WO + bO)
__global__ void attn_ln_kernel(const float* __restrict__ WO, const float* __restrict__ bO,
                               const float* __restrict__ g1, const float* __restrict__ be,
                               const float* __restrict__ hin, int n) {
    __shared__ float As[64 * 68];    // wV/Z rows, then t rows
    __shared__ float Ws[64 * 72];
    int row0 = blockIdx.x * 64;
    int tid = threadIdx.x;
    int w = tid >> 5, lane = tid & 31;
    int g = lane >> 2, t4 = lane & 3;
    int r0 = (w & 3) * 16, n0 = (w >> 2) * 32;

    for (int i = tid; i < 4096; i += 256) Ws[(i >> 6) * 72 + (i & 63)] = WO[i];
    for (int i = tid; i < 4096; i += 256) {
        int r = i >> 6, c = i & 63;
        int gr = row0 + r;
        if (gr < n) {
            float z = g_Z[(size_t)gr * 4 + (c >> 4)] + 1e-6f;
            As[r * 68 + c] = g_wV[(size_t)gr * 64 + c] / z;
        } else {
            As[r * 68 + c] = 0.f;
        }
    }
    __syncthreads();

    float acc[4][4] = {};
    gemm64_tf32<68>(As, Ws, acc, r0, n0);
    __syncthreads();   // reuse As for t

#pragma unroll
    for (int nt = 0; nt < 4; ++nt) {
        int col = n0 + nt * 8 + t4 * 2;
        float2 bb = *(const float2*)&bO[col];
#pragma unroll
        for (int ci = 0; ci < 2; ++ci) {
            int r = r0 + g + 8 * ci;
            int gr = row0 + r;
            if (gr < n) {
                float2 h4 = *(const float2*)&hin[(size_t)gr * 64 + col];
                As[r * 68 + col]     = h4.x + acc[nt][ci * 2]     + bb.x;
                As[r * 68 + col + 1] = h4.y + acc[nt][ci * 2 + 1] + bb.y;
            }
        }
    }
    __syncthreads();

    // LayerNorm: 8 warps x 8 rows
    for (int i = 0; i < 8; ++i) {
        int r = w * 8 + i;
        int gr = row0 + r;
        if (gr >= n) break;
        float x0 = As[r * 68 + lane], x1 = As[r * 68 + lane + 32];
        float s = x0 + x1;
#pragma unroll
        for (int o = 16; o; o >>= 1) s += __shfl_xor_sync(0xffffffffu, s, o);
        float mu = s * (1.f / 64.f);
        float d0 = x0 - mu, d1 = x1 - mu;
        float v = d0 * d0 + d1 * d1;
#pragma unroll
        for (int o = 16; o; o >>= 1) v += __shfl_xor_sync(0xffffffffu, v, o);
        float inv = rsqrtf(v * (1.f / 64.f) + 1e-5f);
        g_h1[(size_t)gr * 64 + lane]      = d0 * inv * g1[lane] + be[lane];
        g_h1[(size_t)gr * 64 + lane + 32] = d1 * inv * g1[lane + 32] + be[lane + 32];
    }
}

// ================= fused FFN (W1+relu, W2) + residual + LayerNorm2 ============
// hout = LN(h1 + relu(h1 @ W1 + b1) @ W2 + b2)
__global__ void ffn_ln_kernel(const float* __restrict__ W1, const float* __restrict__ b1,
                              const float* __restrict__ W2, const float* __restrict__ b2,
                              const float* __restrict__ g1, const float* __restrict__ be,
                              float* __restrict__ hout, int n) {
    __shared__ float h1s[64 * 68];   // h1 rows, later t rows
    __shared__ float Us[64 * 132];   // u rows [64][128] pitch 132
    __shared__ float Ws[64 * 72];
    int row0 = blockIdx.x * 64;
    int tid = threadIdx.x;
    int w = tid >> 5, lane = tid & 31;
    int g = lane >> 2, t4 = lane & 3;
    int r0 = (w & 3) * 16, n0 = (w >> 2) * 32;

    for (int i = tid; i < 4096; i += 256) {
        int r = i >> 6, c = i & 63;
        int gr = row0 + r;
        h1s[r * 68 + c] = (gr < n) ? g_h1[(size_t)gr * 64 + c] : 0.f;
    }

    // ---- GEMM1: u = relu(h1 @ W1 + b1), two 64-col halves ----
#pragma unroll
    for (int nh = 0; nh < 2; ++nh) {
        __syncthreads();
        for (int i = tid; i < 4096; i += 256)
            Ws[(i >> 6) * 72 + (i & 63)] = W1[(size_t)(i >> 6) * 128 + nh * 64 + (i & 63)];
        __syncthreads();

        float acc[4][4] = {};
        gemm64_tf32<68>(h1s, Ws, acc, r0, n0);

#pragma unroll
        for (int nt = 0; nt < 4; ++nt) {
            int col = nh * 64 + n0 + nt * 8 + t4 * 2;
            float2 bb = *(const float2*)&b1[col];
#pragma unroll
            for (int ci = 0; ci < 2; ++ci) {
                int r = r0 + g + 8 * ci;
                Us[r * 132 + col]     = fmaxf(acc[nt][ci * 2]     + bb.x, 0.f);
                Us[r * 132 + col + 1] = fmaxf(acc[nt][ci * 2 + 1] + bb.y, 0.f);
            }
        }
    }

    // ---- GEMM2: t = h1 + u @ W2 + b2, two 64-k halves ----
    float acc2[4][4] = {};
#pragma unroll
    for (int kk = 0; kk < 2; ++kk) {
        __syncthreads();
        for (int i = tid; i < 4096; i += 256)
            Ws[(i >> 6) * 72 + (i & 63)] = W2[(size_t)(kk * 64 + (i >> 6)) * 64 + (i & 63)];
        __syncthreads();
        gemm64_tf32<132>(Us + kk * 64, Ws, acc2, r0, n0);
    }

    // residual + bias into h1s (one thread per cell; no race)
#pragma unroll
    for (int nt = 0; nt < 4; ++nt) {
        int col = n0 + nt * 8 + t4 * 2;
        float2 bb = *(const float2*)&b2[col];
#pragma unroll
        for (int ci = 0; ci < 2; ++ci) {
            int r = r0 + g + 8 * ci;
            h1s[r * 68 + col]     += acc2[nt][ci * 2]     + bb.x;
            h1s[r * 68 + col + 1] += acc2[nt][ci * 2 + 1] + bb.y;
        }
    }
    __syncthreads();

    // LayerNorm2: 8 warps x 8 rows
    for (int i = 0; i < 8; ++i) {
        int r = w * 8 + i;
        int gr = row0 + r;
        if (gr >= n) break;
        float x0 = h1s[r * 68 + lane], x1 = h1s[r * 68 + lane + 32];
        float s = x0 + x1;
#pragma unroll
        for (int o = 16; o; o >>= 1) s += __shfl_xor_sync(0xffffffffu, s, o);
        float mu = s * (1.f / 64.f);
        float d0 = x0 - mu, d1 = x1 - mu;
        float v = d0 * d0 + d1 * d1;
#pragma unroll
        for (int o = 16; o; o >>= 1) v += __shfl_xor_sync(0xffffffffu, v, o);
        float inv = rsqrtf(v * (1.f / 64.f) + 1e-5f);
        hout[(size_t)gr * 64 + lane]      = d0 * inv * g1[lane] + be[lane];
        hout[(size_t)gr * 64 + lane + 32] = d1 * inv * g1[lane + 32] + be[lane + 32];
    }
}

// ---------------- host orchestration ------------------------------------------
extern "C" void kernel_launch(void* const* d_in, const int* in_sizes, int n_in,
                              void* d_out, int out_size) {
    const float* x   = (const float*)d_in[0];
    const float* ea  = (const float*)d_in[1];
    const int*   ei  = (const int*)d_in[2];   // int32 per harness dtype rules
    const float* WQ  = (const float*)d_in[3];
    const float* WK  = (const float*)d_in[4];
    const float* WE  = (const float*)d_in[5];
    const float* WV  = (const float*)d_in[6];
    const float* WO  = (const float*)d_in[7];
    const float* bO  = (const float*)d_in[8];
    const float* g1  = (const float*)d_in[9];
    const float* be1 = (const float*)d_in[10];
    const float* W1  = (const float*)d_in[11];
    const float* b1  = (const float*)d_in[12];
    const float* W2  = (const float*)d_in[13];
    const float* b2  = (const float*)d_in[14];
    const float* g2  = (const float*)d_in[15];
    const float* be2 = (const float*)d_in[16];
    float* out = (float*)d_out;

    int n  = in_sizes[0] / 64;
    int ne = in_sizes[2] / 2;

    float* p_hA;
    cudaGetSymbolAddress((void**)&p_hA, g_hA);

    int nb64 = (n + 63) / 64;
    int nbe  = (ne + 63) / 64;

    for (int l = 0; l < 2; ++l) {
        const float* hin  = l ? p_hA : x;
        float*       hout = l ? out : p_hA;
        size_t wo  = (size_t)l * 64 * 64;
        size_t wo1 = (size_t)l * 64 * 128;
        size_t bo  = (size_t)l * 64;
        size_t bo1 = (size_t)l * 128;

        qkvz_kernel<<<nb64, 256>>>(hin, WQ + wo, WK + wo, WV + wo, n);
        edge_kernel<<<nbe, 256>>>(ea, WE + wo, ei, ne);
        attn_ln_kernel<<<nb64, 256>>>(WO + wo, bO + bo, g1 + bo, be1 + bo, hin, n);
        ffn_ln_kernel<<<nb64, 256>>>(W1 + wo1, b1 + bo1, W2 + wo1, b2 + bo,
                                     g2 + bo, be2 + bo, hout, n);
    }
}